// round 2
// baseline (speedup 1.0000x reference)
#include <cuda_runtime.h>
#include <math.h>

#define BS 16
#define QN 900
#define NC 92
#define TN 256
#define NQT (BS*QN)        // 14400 total queries
#define NT  (BS*TN)        // 4096 total targets
#define C_ELEMS (NQT*NT)   // 58,982,400
#define KSLOT 29           // ceil(900/32)

// ---------------- scratch (static device globals) ----------------------------
__device__ float  g_prob[NQT*NC];       // softmax probs
__device__ float  g_predf[NQT*12];      // cx,cy,w,h,x0,y0,x1,y1,area
__device__ float  g_tgtf[NT*12];
__device__ int    g_tlab[NT];
__device__ float  g_Cb[BS*TN*QN];       // per-batch cost, [b][t][q], fp32 (14.7MB)
__device__ double g_rowmin[BS*TN];      // row minima (duals u init)
__device__ int    g_amin[BS*TN];        // row argmin column

// ---------------- prep: box xyxy + area for preds and targets ---------------
__global__ void prep_boxes_k(const float* __restrict__ pb,
                             const float* __restrict__ tb,
                             const int*   __restrict__ tl) {
    int i = blockIdx.x * blockDim.x + threadIdx.x;
    if (i < NQT) {
        float cx = pb[i*4+0], cy = pb[i*4+1], w = pb[i*4+2], h = pb[i*4+3];
        float x0 = cx - 0.5f*w, y0 = cy - 0.5f*h, x1 = cx + 0.5f*w, y1 = cy + 0.5f*h;
        float* o = &g_predf[i*12];
        o[0]=cx; o[1]=cy; o[2]=w; o[3]=h;
        o[4]=x0; o[5]=y0; o[6]=x1; o[7]=y1;
        o[8]=(x1-x0)*(y1-y0);
    }
    if (i < NT) {
        float cx = tb[i*4+0], cy = tb[i*4+1], w = tb[i*4+2], h = tb[i*4+3];
        float x0 = cx - 0.5f*w, y0 = cy - 0.5f*h, x1 = cx + 0.5f*w, y1 = cy + 0.5f*h;
        float* o = &g_tgtf[i*12];
        o[0]=cx; o[1]=cy; o[2]=w; o[3]=h;
        o[4]=x0; o[5]=y0; o[6]=x1; o[7]=y1;
        o[8]=(x1-x0)*(y1-y0);
        g_tlab[i] = tl[i];
    }
}

// ---------------- softmax: one warp per row of 92 logits --------------------
__global__ void softmax_k(const float* __restrict__ logits) {
    int warp = (blockIdx.x * blockDim.x + threadIdx.x) >> 5;
    int lane = threadIdx.x & 31;
    if (warp >= NQT) return;
    const float* row = logits + warp * NC;
    float v0 = row[lane];
    float v1 = row[lane + 32];
    float v2 = (lane + 64 < NC) ? row[lane + 64] : -INFINITY;
    float m = fmaxf(v0, fmaxf(v1, v2));
    #pragma unroll
    for (int o = 16; o; o >>= 1) m = fmaxf(m, __shfl_xor_sync(0xffffffffu, m, o));
    float e0 = expf(v0 - m), e1 = expf(v1 - m), e2 = expf(v2 - m);
    float s = e0 + e1 + e2;
    #pragma unroll
    for (int o = 16; o; o >>= 1) s += __shfl_xor_sync(0xffffffffu, s, o);
    float* op = g_prob + warp * NC;
    op[lane]      = e0 / s;
    op[lane + 32] = e1 / s;
    if (lane + 64 < NC) op[lane + 64] = e2 / s;
}

// ---------------- fused cost matrix: 16 queries x 256 targets per block -----
__global__ void __launch_bounds__(256) cost_k(float* __restrict__ outC) {
    int jtile = blockIdx.x & 15;        // target tile == batch index
    int itile = blockIdx.x >> 4;        // 900 query tiles of 16
    int tid   = threadIdx.x;
    int jg    = (jtile << 8) + tid;     // global target (column)
    int i0    = itile * 16;

    __shared__ float sprob[16 * NC];
    __shared__ float spred[16 * 12];
    __shared__ float stile[256][17];    // c values for transposed writeout
    for (int k = tid; k < 16 * NC; k += 256) sprob[k] = g_prob[i0 * NC + k];
    for (int k = tid; k < 16 * 12; k += 256) spred[k] = g_predf[i0 * 12 + k];
    __syncthreads();

    const float4* tf = (const float4*)&g_tgtf[jg * 12];
    float4 tc = tf[0];                  // cx cy w h
    float4 txy = tf[1];                 // x0 y0 x1 y1
    float  tarea = g_tgtf[jg * 12 + 8];
    int    lab   = g_tlab[jg];

    #pragma unroll
    for (int ii = 0; ii < 16; ii++) {
        float4 pc  = *(const float4*)&spred[ii * 12];
        float4 pxy = *(const float4*)&spred[ii * 12 + 4];
        float  parea = spred[ii * 12 + 8];
        float  prob  = sprob[ii * NC + lab];

        float l1 = fabsf(pc.x - tc.x) + fabsf(pc.y - tc.y)
                 + fabsf(pc.z - tc.z) + fabsf(pc.w - tc.w);

        float ltx = fmaxf(pxy.x, txy.x), lty = fmaxf(pxy.y, txy.y);
        float rbx = fminf(pxy.z, txy.z), rby = fminf(pxy.w, txy.w);
        float iw = fmaxf(rbx - ltx, 0.0f), ih = fmaxf(rby - lty, 0.0f);
        float inter = iw * ih;
        float uni = parea + tarea - inter;
        float iou = inter / uni;
        float ex0 = fminf(pxy.x, txy.x), ey0 = fminf(pxy.y, txy.y);
        float ex1 = fmaxf(pxy.z, txy.z), ey1 = fmaxf(pxy.w, txy.w);
        float ew = fmaxf(ex1 - ex0, 0.0f), eh = fmaxf(ey1 - ey0, 0.0f);
        float earea = ew * eh;
        float giou = iou - (earea - uni) / earea;

        float c = 5.0f * l1 - prob - 2.0f * giou;
        outC[(size_t)(i0 + ii) * NT + jg] = c;
        stile[tid][ii] = c;
    }
    __syncthreads();

    // transposed writeout of this block's matched-batch slice into g_Cb[b][t][q]
    int bt  = jtile;
    int iiA = bt * QN - i0;         if (iiA < 0)  iiA = 0;
    int iiB = bt * QN + QN - 1 - i0; if (iiB > 15) iiB = 15;
    if (iiA <= iiB) {
        for (int e = tid; e < 256 * 16; e += 256) {
            int t = e >> 4, ii = e & 15;
            if (ii >= iiA && ii <= iiB) {
                int q = i0 + ii - bt * QN;
                g_Cb[(size_t)(bt * TN + t) * QN + q] = stile[t][ii];
            }
        }
    }
}

// ---------------- row minima + argmin: one warp per (b,t) row ---------------
__global__ void __launch_bounds__(256) rowmin_k() {
    int warp = (blockIdx.x * blockDim.x + threadIdx.x) >> 5;
    int lane = threadIdx.x & 31;
    if (warp >= BS * TN) return;
    const float* row = g_Cb + (size_t)warp * QN;
    double bv = 1e300; int bj = QN;
    #pragma unroll
    for (int k = 0; k < KSLOT; k++) {
        int j = lane + (k << 5);
        if (j < QN) {
            double cv = (double)row[j];
            if (cv < bv) { bv = cv; bj = j; }
        }
    }
    #pragma unroll
    for (int o = 16; o; o >>= 1) {
        double ov = __shfl_xor_sync(0xffffffffu, bv, o);
        int    oj = __shfl_xor_sync(0xffffffffu, bj, o);
        if (ov < bv || (ov == bv && oj < bj)) { bv = ov; bj = oj; }
    }
    if (lane == 0) { g_rowmin[warp] = bv; g_amin[warp] = bj; }
}

// ---------------- LSA: Dijkstra successive shortest paths, 1 warp per batch -
__global__ void __launch_bounds__(32) lsa_k(float* __restrict__ out) {
    const int b    = blockIdx.x;
    const int lane = threadIdx.x;
    const float* Cb = g_Cb + (size_t)b * TN * QN;

    __shared__ int    sp[QN];       // column -> assigned row+1 (0 = free)
    __shared__ int    sway[QN];     // Dijkstra predecessor column (-1 = root)
    __shared__ double su[TN];       // row duals
    __shared__ int    pend[TN];
    __shared__ int    npend_s;

    const double DINF = 1e300;

    double v[KSLOT];                // column duals (lane-owned)
    double dist[KSLOT];
    int nslots = (QN - lane + 31) >> 5;
    unsigned validmask = (nslots == KSLOT) ? ((1u << KSLOT) - 1u) : ((1u << (KSLOT-1)) - 1u);
    #pragma unroll
    for (int k = 0; k < KSLOT; k++) v[k] = 0.0;

    for (int j = lane; j < QN; j += 32) sp[j] = 0;
    for (int i = lane; i < TN; i += 32) su[i] = g_rowmin[b * TN + i];
    __syncwarp();

    // greedy seeding (serial on lane 0, trivial work)
    if (lane == 0) {
        int np = 0;
        for (int i = 0; i < TN; i++) {
            int j = g_amin[b * TN + i];
            if (sp[j] == 0) sp[j] = i + 1;
            else pend[np++] = i;
        }
        npend_s = np;
    }
    __syncwarp();
    int npend = npend_s;

    // shortest-path augments for unseeded rows
    for (int pi = 0; pi < npend; pi++) {
        int istart = pend[pi];
        unsigned freem = validmask;
        #pragma unroll
        for (int k = 0; k < KSLOT; k++) dist[k] = DINF;

        double bv = 0.0;
        int i0 = istart, j0 = -1;
        int sink; double minVal;

        while (true) {
            double base = bv - su[i0];
            const float* row = Cb + (size_t)i0 * QN;
            double lbv = DINF; int lbj = QN;
            #pragma unroll
            for (int k = 0; k < KSLOT; k++) {
                if (freem & (1u << k)) {
                    int j = lane + (k << 5);
                    double cur = base + (double)row[j] - v[k];
                    if (cur < dist[k]) { dist[k] = cur; sway[j] = j0; }
                    if (dist[k] < lbv) { lbv = dist[k]; lbj = j; }
                }
            }
            #pragma unroll
            for (int o = 16; o; o >>= 1) {
                double ov = __shfl_xor_sync(0xffffffffu, lbv, o);
                int    oj = __shfl_xor_sync(0xffffffffu, lbj, o);
                if (ov < lbv || (ov == lbv && oj < lbj)) { lbv = ov; lbj = oj; }
            }
            int r = sp[lbj];                 // broadcast LDS
            if (r == 0) { sink = lbj; minVal = lbv; break; }
            if ((lbj & 31) == lane) freem &= ~(1u << (lbj >> 5));
            bv = lbv; j0 = lbj; i0 = r - 1;
        }
        __syncwarp();

        // dual updates (once per augment)
        unsigned usedm = validmask & ~freem;
        #pragma unroll
        for (int k = 0; k < KSLOT; k++) {
            if (usedm & (1u << k)) {
                int j = lane + (k << 5);
                v[k] += dist[k] - minVal;
                int rr = sp[j];              // distinct rows -> conflict-free RMW
                su[rr - 1] += minVal - dist[k];
            }
        }
        __syncwarp();
        if (lane == 0) {
            su[istart] += minVal;
            int j = sink;
            while (true) {
                int jp = sway[j];
                if (jp < 0) { sp[j] = istart + 1; break; }
                sp[j] = sp[jp];
                j = jp;
            }
        }
        __syncwarp();
    }

    if (lane == 0) {
        float* rows = out + (size_t)C_ELEMS + b * TN;
        float* cols = out + (size_t)C_ELEMS + NT + b * TN;
        int k = 0;
        for (int j = 0; j < QN; j++) {
            if (sp[j]) { rows[k] = (float)j; cols[k] = (float)(sp[j] - 1); k++; }
        }
    }
}

// ---------------- launch -----------------------------------------------------
extern "C" void kernel_launch(void* const* d_in, const int* in_sizes, int n_in,
                              void* d_out, int out_size) {
    const float* logits = (const float*)d_in[0];
    const float* pboxes = (const float*)d_in[1];
    const int*   tlab   = (const int*)  d_in[2];
    const float* tbox   = (const float*)d_in[3];
    float* out = (float*)d_out;

    prep_boxes_k<<<(NQT + 255) / 256, 256>>>(pboxes, tbox, tlab);
    softmax_k<<<(NQT * 32 + 255) / 256, 256>>>(logits);
    cost_k<<<14400, 256>>>(out);
    rowmin_k<<<(BS * TN) / 8, 256>>>();
    lsa_k<<<BS, 32>>>(out);
}

// round 3
// speedup vs baseline: 4.2021x; 4.2021x over previous
#include <cuda_runtime.h>
#include <math.h>

#define BS 16
#define QN 900
#define NC 92
#define TN 256
#define NQT (BS*QN)        // 14400 total queries
#define NT  (BS*TN)        // 4096 total targets
#define C_ELEMS (NQT*NT)   // 58,982,400

// fixed-point scale 2^40 (exact for |c| >= 2^-17; error < 2^-41 otherwise)
#define FP_SCALE 1099511627776.0
#define I64_INF  (1LL<<62)

// ---------------- scratch (static device globals) ----------------------------
__device__ float      g_prob[NQT*NC];     // softmax probs
__device__ float      g_predf[NQT*12];    // cx,cy,w,h,x0,y0,x1,y1,area
__device__ float      g_tgtf[NT*12];
__device__ int        g_tlab[NT];
__device__ long long  g_Ci[BS*TN*QN];     // per-batch cost, [b][t][q], int64 fixed-pt (29.5MB)
__device__ long long  g_rowminI[BS*TN];   // row minima (dual u init)
__device__ int        g_amin[BS*TN];      // row argmin column

// ---------------- prep: box xyxy + area for preds and targets ---------------
__global__ void prep_boxes_k(const float* __restrict__ pb,
                             const float* __restrict__ tb,
                             const int*   __restrict__ tl) {
    int i = blockIdx.x * blockDim.x + threadIdx.x;
    if (i < NQT) {
        float cx = pb[i*4+0], cy = pb[i*4+1], w = pb[i*4+2], h = pb[i*4+3];
        float x0 = cx - 0.5f*w, y0 = cy - 0.5f*h, x1 = cx + 0.5f*w, y1 = cy + 0.5f*h;
        float* o = &g_predf[i*12];
        o[0]=cx; o[1]=cy; o[2]=w; o[3]=h;
        o[4]=x0; o[5]=y0; o[6]=x1; o[7]=y1;
        o[8]=(x1-x0)*(y1-y0);
    }
    if (i < NT) {
        float cx = tb[i*4+0], cy = tb[i*4+1], w = tb[i*4+2], h = tb[i*4+3];
        float x0 = cx - 0.5f*w, y0 = cy - 0.5f*h, x1 = cx + 0.5f*w, y1 = cy + 0.5f*h;
        float* o = &g_tgtf[i*12];
        o[0]=cx; o[1]=cy; o[2]=w; o[3]=h;
        o[4]=x0; o[5]=y0; o[6]=x1; o[7]=y1;
        o[8]=(x1-x0)*(y1-y0);
        g_tlab[i] = tl[i];
    }
}

// ---------------- softmax: one warp per row of 92 logits --------------------
__global__ void softmax_k(const float* __restrict__ logits) {
    int warp = (blockIdx.x * blockDim.x + threadIdx.x) >> 5;
    int lane = threadIdx.x & 31;
    if (warp >= NQT) return;
    const float* row = logits + warp * NC;
    float v0 = row[lane];
    float v1 = row[lane + 32];
    float v2 = (lane + 64 < NC) ? row[lane + 64] : -INFINITY;
    float m = fmaxf(v0, fmaxf(v1, v2));
    #pragma unroll
    for (int o = 16; o; o >>= 1) m = fmaxf(m, __shfl_xor_sync(0xffffffffu, m, o));
    float e0 = expf(v0 - m), e1 = expf(v1 - m), e2 = expf(v2 - m);
    float s = e0 + e1 + e2;
    #pragma unroll
    for (int o = 16; o; o >>= 1) s += __shfl_xor_sync(0xffffffffu, s, o);
    float* op = g_prob + warp * NC;
    op[lane]      = e0 / s;
    op[lane + 32] = e1 / s;
    if (lane + 64 < NC) op[lane + 64] = e2 / s;
}

// ---------------- fused cost matrix: 16 queries x 256 targets per block -----
__global__ void __launch_bounds__(256) cost_k(float* __restrict__ outC) {
    int jtile = blockIdx.x & 15;        // target tile == batch index
    int itile = blockIdx.x >> 4;        // 900 query tiles of 16
    int tid   = threadIdx.x;
    int jg    = (jtile << 8) + tid;     // global target (column)
    int i0    = itile * 16;

    __shared__ float sprob[16 * NC];
    __shared__ float spred[16 * 12];
    __shared__ float stile[256][17];    // c values for transposed writeout
    for (int k = tid; k < 16 * NC; k += 256) sprob[k] = g_prob[i0 * NC + k];
    for (int k = tid; k < 16 * 12; k += 256) spred[k] = g_predf[i0 * 12 + k];
    __syncthreads();

    const float4* tf = (const float4*)&g_tgtf[jg * 12];
    float4 tc = tf[0];                  // cx cy w h
    float4 txy = tf[1];                 // x0 y0 x1 y1
    float  tarea = g_tgtf[jg * 12 + 8];
    int    lab   = g_tlab[jg];

    #pragma unroll
    for (int ii = 0; ii < 16; ii++) {
        float4 pc  = *(const float4*)&spred[ii * 12];
        float4 pxy = *(const float4*)&spred[ii * 12 + 4];
        float  parea = spred[ii * 12 + 8];
        float  prob  = sprob[ii * NC + lab];

        float l1 = fabsf(pc.x - tc.x) + fabsf(pc.y - tc.y)
                 + fabsf(pc.z - tc.z) + fabsf(pc.w - tc.w);

        float ltx = fmaxf(pxy.x, txy.x), lty = fmaxf(pxy.y, txy.y);
        float rbx = fminf(pxy.z, txy.z), rby = fminf(pxy.w, txy.w);
        float iw = fmaxf(rbx - ltx, 0.0f), ih = fmaxf(rby - lty, 0.0f);
        float inter = iw * ih;
        float uni = parea + tarea - inter;
        float iou = inter / uni;
        float ex0 = fminf(pxy.x, txy.x), ey0 = fminf(pxy.y, txy.y);
        float ex1 = fmaxf(pxy.z, txy.z), ey1 = fmaxf(pxy.w, txy.w);
        float ew = fmaxf(ex1 - ex0, 0.0f), eh = fmaxf(ey1 - ey0, 0.0f);
        float earea = ew * eh;
        float giou = iou - (earea - uni) / earea;

        float c = 5.0f * l1 - prob - 2.0f * giou;
        outC[(size_t)(i0 + ii) * NT + jg] = c;
        stile[tid][ii] = c;
    }
    __syncthreads();

    // transposed int64 fixed-point writeout of this block's batch slice
    int bt  = jtile;
    int iiA = bt * QN - i0;          if (iiA < 0)  iiA = 0;
    int iiB = bt * QN + QN - 1 - i0; if (iiB > 15) iiB = 15;
    if (iiA <= iiB) {
        for (int e = tid; e < 256 * 16; e += 256) {
            int t = e >> 4, ii = e & 15;
            if (ii >= iiA && ii <= iiB) {
                int q = i0 + ii - bt * QN;
                g_Ci[(size_t)(bt * TN + t) * QN + q] =
                    __double2ll_rn((double)stile[t][ii] * FP_SCALE);
            }
        }
    }
}

// ---------------- row minima + argmin: one warp per (b,t) row, int64 --------
__global__ void __launch_bounds__(256) rowmin_k() {
    int warp = (blockIdx.x * blockDim.x + threadIdx.x) >> 5;
    int lane = threadIdx.x & 31;
    if (warp >= BS * TN) return;
    const long long* row = g_Ci + (size_t)warp * QN;
    long long bv = I64_INF; int bj = QN;
    #pragma unroll
    for (int k = 0; k < 29; k++) {
        int j = lane + (k << 5);
        if (j < QN) {
            long long cv = row[j];
            if (cv < bv) { bv = cv; bj = j; }
        }
    }
    #pragma unroll
    for (int o = 16; o; o >>= 1) {
        long long ov = __shfl_xor_sync(0xffffffffu, bv, o);
        int       oj = __shfl_xor_sync(0xffffffffu, bj, o);
        if (ov < bv || (ov == bv && oj < bj)) { bv = ov; bj = oj; }
    }
    if (lane == 0) { g_rowminI[warp] = bv; g_amin[warp] = bj; }
}

// ---------------- LSA: Dijkstra SSP, int64 exact, 1 block/batch, 256 thr ----
// thread tid owns columns j = tid + 256k, k = 0..3 (j < 900)
__global__ void __launch_bounds__(256) lsa_k(float* __restrict__ out) {
    const int b   = blockIdx.x;
    const int tid = threadIdx.x;
    const int lane = tid & 31;
    const int wrp  = tid >> 5;
    const long long* Cb = g_Ci + (size_t)b * TN * QN;

    __shared__ int       sp[QN];      // column -> row+1 (0 free)
    __shared__ int       sway[QN];    // predecessor column (-1 root)
    __shared__ long long su[TN];      // row duals
    __shared__ int       pend[TN];
    __shared__ int       npend_s;
    __shared__ long long wval[8];
    __shared__ int       widx[8];
    __shared__ int       sj0;
    __shared__ long long sbv;

    long long v[4], dist[4];
    unsigned validm = 0;
    #pragma unroll
    for (int k = 0; k < 4; k++) {
        if (tid + (k << 8) < QN) validm |= 1u << k;
        v[k] = 0;
    }

    for (int j = tid; j < QN; j += 256) sp[j] = 0;
    for (int i = tid; i < TN; i += 256) su[i] = g_rowminI[b * TN + i];
    __syncthreads();

    // greedy seeding (serial on thread 0)
    if (tid == 0) {
        int np = 0;
        for (int i = 0; i < TN; i++) {
            int j = g_amin[b * TN + i];
            if (sp[j] == 0) sp[j] = i + 1;
            else pend[np++] = i;
        }
        npend_s = np;
    }
    __syncthreads();
    int npend = npend_s;

    for (int pi = 0; pi < npend; pi++) {
        int istart = pend[pi];
        unsigned freem = validm;
        #pragma unroll
        for (int k = 0; k < 4; k++) dist[k] = I64_INF;

        long long bv = 0;
        int i0r = istart, j0 = -1;
        int sink; long long minVal;

        while (true) {
            long long base = bv - su[i0r];
            const long long* row = Cb + (size_t)i0r * QN;

            long long lbv = I64_INF; int lbj = QN;
            #pragma unroll
            for (int k = 0; k < 4; k++) {
                if (freem & (1u << k)) {
                    int j = tid + (k << 8);
                    long long cur = base + row[j] - v[k];
                    if (cur < dist[k]) { dist[k] = cur; sway[j] = j0; }
                    if (dist[k] < lbv) { lbv = dist[k]; lbj = j; }
                }
            }
            #pragma unroll
            for (int o = 16; o; o >>= 1) {
                long long ov = __shfl_down_sync(0xffffffffu, lbv, o);
                int       oj = __shfl_down_sync(0xffffffffu, lbj, o);
                if (ov < lbv || (ov == lbv && oj < lbj)) { lbv = ov; lbj = oj; }
            }
            if (lane == 0) { wval[wrp] = lbv; widx[wrp] = lbj; }
            __syncthreads();
            if (tid == 0) {
                long long vv = wval[0]; int jj = widx[0];
                #pragma unroll
                for (int w = 1; w < 8; w++)
                    if (wval[w] < vv || (wval[w] == vv && widx[w] < jj)) { vv = wval[w]; jj = widx[w]; }
                sj0 = jj; sbv = vv;
            }
            __syncthreads();

            int jj = sj0;
            bv = sbv;
            if ((jj & 255) == tid) freem &= ~(1u << (jj >> 8));   // owner removes col
            int r = sp[jj];                                        // broadcast LDS
            if (r == 0) { sink = jj; minVal = bv; break; }
            j0 = jj; i0r = r - 1;
        }

        // dual updates (once per augment), exact int64
        unsigned usedm = validm & ~freem;
        #pragma unroll
        for (int k = 0; k < 4; k++) {
            if (usedm & (1u << k)) {
                int j = tid + (k << 8);
                long long d = dist[k];
                v[k] += d - minVal;
                su[sp[j] - 1] += minVal - d;   // distinct rows -> conflict-free
            }
        }
        __syncthreads();
        if (tid == 0) {
            su[istart] += minVal;
            int j = sink;
            while (true) {
                int jp = sway[j];
                if (jp < 0) { sp[j] = istart + 1; break; }
                sp[j] = sp[jp];
                j = jp;
            }
        }
        __syncthreads();
    }

    if (tid == 0) {
        float* rows = out + (size_t)C_ELEMS + b * TN;
        float* cols = out + (size_t)C_ELEMS + NT + b * TN;
        int k = 0;
        for (int j = 0; j < QN; j++) {
            if (sp[j]) { rows[k] = (float)j; cols[k] = (float)(sp[j] - 1); k++; }
        }
    }
}

// ---------------- launch -----------------------------------------------------
extern "C" void kernel_launch(void* const* d_in, const int* in_sizes, int n_in,
                              void* d_out, int out_size) {
    const float* logits = (const float*)d_in[0];
    const float* pboxes = (const float*)d_in[1];
    const int*   tlab   = (const int*)  d_in[2];
    const float* tbox   = (const float*)d_in[3];
    float* out = (float*)d_out;

    prep_boxes_k<<<(NQT + 255) / 256, 256>>>(pboxes, tbox, tlab);
    softmax_k<<<(NQT * 32 + 255) / 256, 256>>>(logits);
    cost_k<<<14400, 256>>>(out);
    rowmin_k<<<(BS * TN) / 8, 256>>>();
    lsa_k<<<BS, 256>>>(out);
}

// round 4
// speedup vs baseline: 4.7810x; 1.1378x over previous
#include <cuda_runtime.h>
#include <math.h>

#define BS 16
#define QN 900
#define NC 92
#define TN 256
#define NQT (BS*QN)        // 14400
#define NT  (BS*TN)        // 4096
#define C_ELEMS (NQT*NT)   // 58,982,400

#define FP_SCALE_F 1099511627776.0f   // 2^40
#define I64_INF  (1LL<<62)
#define KEY_BIAS (1LL<<45)

// ---------------- scratch ----------------------------------------------------
__device__ float      g_prob[NQT*NC];
__device__ float      g_predf[NQT*12];
__device__ float      g_tgtf[NT*12];
__device__ int        g_tlab[NT];
__device__ long long  g_Ci[BS*TN*QN];     // [b][t][q] int64 fixed-point
__device__ long long  g_rowkey[BS*TN];    // packed (min value, argmin col)

__device__ __forceinline__ int tmin_of(int b) { return (900 * b) >> 4; }
__device__ __forceinline__ int tmax_of(int b) { return (900 * b + 899) >> 4; }

// ---------------- prep -------------------------------------------------------
__global__ void prep_boxes_k(const float* __restrict__ pb,
                             const float* __restrict__ tb,
                             const int*   __restrict__ tl) {
    int i = blockIdx.x * blockDim.x + threadIdx.x;
    if (i < NQT) {
        float cx = pb[i*4+0], cy = pb[i*4+1], w = pb[i*4+2], h = pb[i*4+3];
        float x0 = cx - 0.5f*w, y0 = cy - 0.5f*h, x1 = cx + 0.5f*w, y1 = cy + 0.5f*h;
        float* o = &g_predf[i*12];
        o[0]=cx; o[1]=cy; o[2]=w; o[3]=h;
        o[4]=x0; o[5]=y0; o[6]=x1; o[7]=y1;
        o[8]=(x1-x0)*(y1-y0);
    }
    if (i < NT) {
        float cx = tb[i*4+0], cy = tb[i*4+1], w = tb[i*4+2], h = tb[i*4+3];
        float x0 = cx - 0.5f*w, y0 = cy - 0.5f*h, x1 = cx + 0.5f*w, y1 = cy + 0.5f*h;
        float* o = &g_tgtf[i*12];
        o[0]=cx; o[1]=cy; o[2]=w; o[3]=h;
        o[4]=x0; o[5]=y0; o[6]=x1; o[7]=y1;
        o[8]=(x1-x0)*(y1-y0);
        g_tlab[i] = tl[i];
        g_rowkey[i] = I64_INF;            // reinit every call (graph-replay safe)
    }
}

// ---------------- softmax ----------------------------------------------------
__global__ void softmax_k(const float* __restrict__ logits) {
    int warp = (blockIdx.x * blockDim.x + threadIdx.x) >> 5;
    int lane = threadIdx.x & 31;
    if (warp >= NQT) return;
    const float* row = logits + warp * NC;
    float v0 = row[lane];
    float v1 = row[lane + 32];
    float v2 = (lane + 64 < NC) ? row[lane + 64] : -INFINITY;
    float m = fmaxf(v0, fmaxf(v1, v2));
    #pragma unroll
    for (int o = 16; o; o >>= 1) m = fmaxf(m, __shfl_xor_sync(0xffffffffu, m, o));
    float e0 = expf(v0 - m), e1 = expf(v1 - m), e2 = expf(v2 - m);
    float s = e0 + e1 + e2;
    #pragma unroll
    for (int o = 16; o; o >>= 1) s += __shfl_xor_sync(0xffffffffu, s, o);
    float* op = g_prob + warp * NC;
    op[lane]      = e0 / s;
    op[lane + 32] = e1 / s;
    if (lane + 64 < NC) op[lane + 64] = e2 / s;
}

// ---------------- shared cost-pair math --------------------------------------
__device__ __forceinline__ float cost_pair(const float* __restrict__ spred, int ii,
                                           float prob, float4 tc, float4 txy, float tarea) {
    float4 pc  = *(const float4*)&spred[ii * 12];
    float4 pxy = *(const float4*)&spred[ii * 12 + 4];
    float  parea = spred[ii * 12 + 8];

    float l1 = fabsf(pc.x - tc.x) + fabsf(pc.y - tc.y)
             + fabsf(pc.z - tc.z) + fabsf(pc.w - tc.w);

    float ltx = fmaxf(pxy.x, txy.x), lty = fmaxf(pxy.y, txy.y);
    float rbx = fminf(pxy.z, txy.z), rby = fminf(pxy.w, txy.w);
    float iw = fmaxf(rbx - ltx, 0.0f), ih = fmaxf(rby - lty, 0.0f);
    float inter = iw * ih;
    float uni = parea + tarea - inter;
    float iou = inter / uni;
    float ex0 = fminf(pxy.x, txy.x), ey0 = fminf(pxy.y, txy.y);
    float ex1 = fmaxf(pxy.z, txy.z), ey1 = fmaxf(pxy.w, txy.w);
    float ew = fmaxf(ex1 - ex0, 0.0f), eh = fmaxf(ey1 - ey0, 0.0f);
    float earea = ew * eh;
    float giou = iou - (earea - uni) / earea;

    return 5.0f * l1 - prob - 2.0f * giou;
}

// ---------------- diagonal cost tiles: outC + g_Ci + atomic rowmin ----------
__global__ void __launch_bounds__(256) cost_diag_k(float* __restrict__ outC) {
    int b     = blockIdx.y;
    int itile = tmin_of(b) + blockIdx.x;
    if (itile > tmax_of(b)) return;
    int tid = threadIdx.x;
    int jg  = (b << 8) + tid;
    int i0  = itile * 16;

    __shared__ float sprob[16 * NC];
    __shared__ float spred[16 * 12];
    __shared__ float stile[256][17];
    for (int k = tid; k < 16 * NC; k += 256) sprob[k] = g_prob[i0 * NC + k];
    for (int k = tid; k < 16 * 12; k += 256) spred[k] = g_predf[i0 * 12 + k];
    __syncthreads();

    const float4* tf = (const float4*)&g_tgtf[jg * 12];
    float4 tc = tf[0];
    float4 txy = tf[1];
    float  tarea = g_tgtf[jg * 12 + 8];
    int    lab   = g_tlab[jg];

    int iiA = b * QN - i0;           if (iiA < 0)  iiA = 0;
    int iiB = b * QN + QN - 1 - i0;  if (iiB > 15) iiB = 15;

    long long bestkey = I64_INF;
    #pragma unroll
    for (int ii = 0; ii < 16; ii++) {
        float prob = sprob[ii * NC + lab];
        float c = cost_pair(spred, ii, prob, tc, txy, tarea);
        outC[(size_t)(i0 + ii) * NT + jg] = c;
        stile[tid][ii] = c;
        if (ii >= iiA && ii <= iiB) {
            long long ci = llrintf(c * FP_SCALE_F);
            int q = i0 + ii - b * QN;
            long long key = ((ci + KEY_BIAS) << 10) | (long long)q;
            if (key < bestkey) bestkey = key;
        }
    }
    if (bestkey != I64_INF) atomicMin(&g_rowkey[jg], bestkey);
    __syncthreads();

    // transposed int64 writeout into g_Ci[b][t][q]
    for (int e = tid; e < 256 * 16; e += 256) {
        int t = e >> 4, ii = e & 15;
        if (ii >= iiA && ii <= iiB) {
            int q = i0 + ii - b * QN;
            g_Ci[(size_t)((b << 8) + t) * QN + q] = llrintf(stile[t][ii] * FP_SCALE_F);
        }
    }
}

// ---------------- LSA device routine (one 256-thread block per batch) -------
__device__ void lsa_block(int b, float* __restrict__ out) {
    const int tid  = threadIdx.x;
    const int lane = tid & 31;
    const int wrp  = tid >> 5;
    const long long* Cb = g_Ci + (size_t)b * TN * QN;

    __shared__ int       sp[QN];
    __shared__ int       sway[QN];
    __shared__ long long su[TN];
    __shared__ int       pend[TN];
    __shared__ int       npend_s;
    __shared__ long long wval[8];
    __shared__ int       widx[8];
    __shared__ int       sj0;
    __shared__ long long sbv;

    long long v[4], dist[4];
    unsigned validm = 0;
    #pragma unroll
    for (int k = 0; k < 4; k++) {
        if (tid + (k << 8) < QN) validm |= 1u << k;
        v[k] = 0;
    }

    for (int j = tid; j < QN; j += 256) sp[j] = 0;
    for (int i = tid; i < TN; i += 256)
        su[i] = (g_rowkey[b * TN + i] >> 10) - KEY_BIAS;
    __syncthreads();

    if (tid == 0) {
        int np = 0;
        for (int i = 0; i < TN; i++) {
            int j = (int)(g_rowkey[b * TN + i] & 1023LL);
            if (sp[j] == 0) sp[j] = i + 1;
            else pend[np++] = i;
        }
        npend_s = np;
    }
    __syncthreads();
    int npend = npend_s;

    for (int pi = 0; pi < npend; pi++) {
        int istart = pend[pi];
        unsigned freem = validm;
        #pragma unroll
        for (int k = 0; k < 4; k++) dist[k] = I64_INF;

        long long bv = 0;
        int i0r = istart, j0 = -1;
        int sink; long long minVal;

        while (true) {
            long long base = bv - su[i0r];
            const long long* row = Cb + (size_t)i0r * QN;

            long long lbv = I64_INF; int lbj = QN;
            #pragma unroll
            for (int k = 0; k < 4; k++) {
                if (freem & (1u << k)) {
                    int j = tid + (k << 8);
                    long long cur = base + row[j] - v[k];
                    if (cur < dist[k]) { dist[k] = cur; sway[j] = j0; }
                    if (dist[k] < lbv) { lbv = dist[k]; lbj = j; }
                }
            }
            #pragma unroll
            for (int o = 16; o; o >>= 1) {
                long long ov = __shfl_down_sync(0xffffffffu, lbv, o);
                int       oj = __shfl_down_sync(0xffffffffu, lbj, o);
                if (ov < lbv || (ov == lbv && oj < lbj)) { lbv = ov; lbj = oj; }
            }
            if (lane == 0) { wval[wrp] = lbv; widx[wrp] = lbj; }
            __syncthreads();
            if (tid == 0) {
                long long vv = wval[0]; int jj = widx[0];
                #pragma unroll
                for (int w = 1; w < 8; w++)
                    if (wval[w] < vv || (wval[w] == vv && widx[w] < jj)) { vv = wval[w]; jj = widx[w]; }
                sj0 = jj; sbv = vv;
            }
            __syncthreads();

            int jj = sj0;
            bv = sbv;
            if ((jj & 255) == tid) freem &= ~(1u << (jj >> 8));
            int r = sp[jj];
            if (r == 0) { sink = jj; minVal = bv; break; }
            j0 = jj; i0r = r - 1;
        }

        unsigned usedm = validm & ~freem;
        #pragma unroll
        for (int k = 0; k < 4; k++) {
            if (usedm & (1u << k)) {
                int j = tid + (k << 8);
                long long d = dist[k];
                v[k] += d - minVal;
                su[sp[j] - 1] += minVal - d;
            }
        }
        __syncthreads();
        if (tid == 0) {
            su[istart] += minVal;
            int j = sink;
            while (true) {
                int jp = sway[j];
                if (jp < 0) { sp[j] = istart + 1; break; }
                sp[j] = sp[jp];
                j = jp;
            }
        }
        __syncthreads();
    }

    if (tid == 0) {
        float* rows = out + (size_t)C_ELEMS + b * TN;
        float* cols = out + (size_t)C_ELEMS + NT + b * TN;
        int k = 0;
        for (int j = 0; j < QN; j++) {
            if (sp[j]) { rows[k] = (float)j; cols[k] = (float)(sp[j] - 1); k++; }
        }
    }
}

// ---------------- fused: LSA (bid<16) + off-diagonal cost tiles --------------
__global__ void __launch_bounds__(256) fused_k(float* __restrict__ outC) {
    if (blockIdx.x < 16) { lsa_block(blockIdx.x, outC); return; }

    int e = blockIdx.x - 16;
    int itile = e >> 4;
    int jtile = e & 15;
    if (itile >= tmin_of(jtile) && itile <= tmax_of(jtile)) return;  // diag done

    int tid = threadIdx.x;
    int jg  = (jtile << 8) + tid;
    int i0  = itile * 16;

    __shared__ float sprob[16 * NC];
    __shared__ float spred[16 * 12];
    for (int k = tid; k < 16 * NC; k += 256) sprob[k] = g_prob[i0 * NC + k];
    for (int k = tid; k < 16 * 12; k += 256) spred[k] = g_predf[i0 * 12 + k];
    __syncthreads();

    const float4* tf = (const float4*)&g_tgtf[jg * 12];
    float4 tc = tf[0];
    float4 txy = tf[1];
    float  tarea = g_tgtf[jg * 12 + 8];
    int    lab   = g_tlab[jg];

    #pragma unroll
    for (int ii = 0; ii < 16; ii++) {
        float prob = sprob[ii * NC + lab];
        float c = cost_pair(spred, ii, prob, tc, txy, tarea);
        outC[(size_t)(i0 + ii) * NT + jg] = c;
    }
}

// ---------------- launch -----------------------------------------------------
extern "C" void kernel_launch(void* const* d_in, const int* in_sizes, int n_in,
                              void* d_out, int out_size) {
    const float* logits = (const float*)d_in[0];
    const float* pboxes = (const float*)d_in[1];
    const int*   tlab   = (const int*)  d_in[2];
    const float* tbox   = (const float*)d_in[3];
    float* out = (float*)d_out;

    prep_boxes_k<<<(NQT + 255) / 256, 256>>>(pboxes, tbox, tlab);
    softmax_k<<<(NQT * 32 + 255) / 256, 256>>>(logits);
    cost_diag_k<<<dim3(58, 16), 256>>>(out);
    fused_k<<<16 + NQT, 256>>>(out);
}